// round 1
// baseline (speedup 1.0000x reference)
#include <cuda_runtime.h>

#define N_NODES  20000
#define N_EDGES  40000
#define N_GRAPHS 500
#define D_IN     32
#define D_E      16
#define H1       100
#define H2       20
#define F1       50

// ---------------- scratch (static device arrays; no allocs allowed) --------
__device__ float d_agg1[N_NODES * H1];   // layer-1 aggregated messages
__device__ float d_h1  [N_NODES * H1];   // layer-1 output features
__device__ float d_agg2[N_NODES * H2];   // layer-2 aggregated messages
__device__ float d_g   [N_GRAPHS * H2];  // pooled graph features
__device__ float d_g1  [N_GRAPHS * F1];  // FCN hidden
__device__ int   d_is64;                 // 1 if edge_index/batch are int64

// ---------------- dtype detection (int32 vs int64 indices) -----------------
// For little-endian int64 with values < 2^31, every odd 32-bit word is 0.
// For genuine int32 data those words are random indices -> OR != 0.
__global__ void detect_kernel(const unsigned int* __restrict__ ei_words) {
    __shared__ unsigned int red[256];
    unsigned int v = 0;
    for (int i = threadIdx.x; i < N_EDGES; i += blockDim.x)
        v |= ei_words[2 * i + 1];
    red[threadIdx.x] = v;
    __syncthreads();
    for (int s = 128; s > 0; s >>= 1) {
        if (threadIdx.x < s) red[threadIdx.x] |= red[threadIdx.x + s];
        __syncthreads();
    }
    if (threadIdx.x == 0) d_is64 = (red[0] == 0u) ? 1 : 0;
}

// ---------------- zero the accumulators -------------------------------------
#define Z_TOTAL (N_NODES * H1 + N_NODES * H2 + N_GRAPHS * H2)
__global__ void zero_kernel() {
    int i = blockIdx.x * blockDim.x + threadIdx.x;
    if (i < N_NODES * H1) d_agg1[i] = 0.f;
    else if (i < N_NODES * H1 + N_NODES * H2) d_agg2[i - N_NODES * H1] = 0.f;
    else if (i < Z_TOTAL) d_g[i - N_NODES * H1 - N_NODES * H2] = 0.f;
}

// ---------------- fused edge GEMM + scatter ---------------------------------
// msg_e[o] = sum_{k<16, i<D} ea[e][k] * feat[src[e]][i] * W[k][i*O + o]
//          + sum_{i<D}       feat[src[e]][i] * bias[i*O + o]
// A-matrix [E, 17*D] generated on the fly in smem; atomicAdd into agg[dst].
template<int D, int O, int TM, int RE, int RO, int NT>
__global__ void __launch_bounds__(NT) edge_gemm(
    const float* __restrict__ feat,   // [N, D]
    const float* __restrict__ ea,     // [E, 16]
    const void*  __restrict__ ei_raw, // [2, E] int32 or int64
    const float* __restrict__ W,      // [16, D*O]
    const float* __restrict__ bias,   // [D*O]
    float*       __restrict__ agg)    // [N, O]
{
    constexpr int KW = 16;
    constexpr int OG = O / RO;

    __shared__ float ea_s[TM][D_E];
    __shared__ float f_s [TM][D];
    __shared__ float A_s [KW][TM];
    __shared__ float W_s [KW][O];
    __shared__ int   src_s[TM];
    __shared__ int   dst_s[TM];

    const int tid = threadIdx.x;
    const int e0  = blockIdx.x * TM;

    if (tid < TM) {
        int e = e0 + tid;
        if (d_is64) {
            const long long* p = (const long long*)ei_raw;
            src_s[tid] = (int)p[e];
            dst_s[tid] = (int)p[N_EDGES + e];
        } else {
            const int* p = (const int*)ei_raw;
            src_s[tid] = p[e];
            dst_s[tid] = p[N_EDGES + e];
        }
    }
    __syncthreads();
    for (int idx = tid; idx < TM * D_E; idx += NT) {
        int r = idx / D_E, c = idx % D_E;
        ea_s[r][c] = ea[(e0 + r) * D_E + c];
    }
    for (int idx = tid; idx < TM * D; idx += NT) {
        int r = idx / D, c = idx % D;
        f_s[r][c] = feat[src_s[r] * D + c];
    }
    __syncthreads();

    const int r0 = (tid / OG) * RE;
    const int o0 = (tid % OG) * RO;

    float acc[RE][RO];
    #pragma unroll
    for (int a = 0; a < RE; a++)
        #pragma unroll
        for (int b = 0; b < RO; b++) acc[a][b] = 0.f;

    constexpr int MAIN_TILES = D;                 // 16*D / KW
    constexpr int BIAS_TILES = (D + KW - 1) / KW;

    for (int t = 0; t < MAIN_TILES + BIAS_TILES; ++t) {
        // stage A tile: A_s[kl][r]
        for (int idx = tid; idx < KW * TM; idx += NT) {
            int kl = idx / TM, r = idx % TM;
            int kg = t * KW + kl;
            float a;
            if (t < MAIN_TILES) {
                int kk = kg / D, i = kg % D;
                a = ea_s[r][kk] * f_s[r][i];
            } else {
                int i = kg - 16 * D;
                a = (i < D) ? f_s[r][i] : 0.f;
            }
            A_s[kl][r] = a;
        }
        // stage W tile: W_s[kl][o]
        for (int idx = tid; idx < KW * O; idx += NT) {
            int kl = idx / O, o = idx % O;
            int kg = t * KW + kl;
            float w;
            if (t < MAIN_TILES) {
                int kk = kg / D, i = kg % D;
                w = W[kk * (D * O) + i * O + o];
            } else {
                int i = kg - 16 * D;
                w = (i < D) ? bias[i * O + o] : 0.f;
            }
            W_s[kl][o] = w;
        }
        __syncthreads();
        #pragma unroll
        for (int k = 0; k < KW; ++k) {
            float av[RE];
            if (RE == 4) {
                float4 v = *reinterpret_cast<const float4*>(&A_s[k][r0]);
                av[0] = v.x; av[1] = v.y; av[2] = v.z; av[3] = v.w;
            } else {
                #pragma unroll
                for (int jr = 0; jr < RE; ++jr) av[jr] = A_s[k][r0 + jr];
            }
            #pragma unroll
            for (int j = 0; j < RO; ++j) {
                float w = W_s[k][o0 + j];
                #pragma unroll
                for (int jr = 0; jr < RE; ++jr)
                    acc[jr][j] = fmaf(av[jr], w, acc[jr][j]);
            }
        }
        __syncthreads();
    }

    #pragma unroll
    for (int jr = 0; jr < RE; ++jr) {
        int dn = dst_s[r0 + jr];
        #pragma unroll
        for (int j = 0; j < RO; ++j)
            atomicAdd(&agg[dn * O + o0 + j], acc[jr][j]);
    }
}

// ---------------- node update 1: h1 = relu(agg1 + x@root1 + bias1) ---------
__global__ void __launch_bounds__(512) node1_kernel(
    const float* __restrict__ x,
    const float* __restrict__ root1,
    const float* __restrict__ bias1)
{
    __shared__ float x_s[4][D_IN];
    int n0  = blockIdx.x * 4;
    int tid = threadIdx.x;
    if (tid < 4 * D_IN)
        x_s[tid / D_IN][tid % D_IN] = x[(n0 + tid / D_IN) * D_IN + tid % D_IN];
    __syncthreads();
    int nl = tid / 128;
    int o  = tid % 128;
    if (o < H1) {
        int n = n0 + nl;
        float acc = d_agg1[n * H1 + o] + bias1[o];
        #pragma unroll
        for (int i = 0; i < D_IN; ++i)
            acc = fmaf(x_s[nl][i], root1[i * H1 + o], acc);
        d_h1[n * H1 + o] = fmaxf(acc, 0.f);
    }
}

// ---------------- node update 2 + sum-pool ----------------------------------
__global__ void __launch_bounds__(256) node2_kernel(
    const float* __restrict__ root2,
    const float* __restrict__ bias2,
    const void*  __restrict__ batch_raw)
{
    __shared__ float h_s[8][H1];
    __shared__ int   g_s[8];
    int n0  = blockIdx.x * 8;
    int tid = threadIdx.x;
    for (int idx = tid; idx < 8 * H1; idx += 256)
        h_s[idx / H1][idx % H1] = d_h1[(n0 + idx / H1) * H1 + idx % H1];
    if (tid < 8) {
        int n = n0 + tid;
        g_s[tid] = d_is64 ? (int)((const long long*)batch_raw)[n]
                          : ((const int*)batch_raw)[n];
    }
    __syncthreads();
    int nl = tid / 32;
    int o  = tid % 32;
    if (o < H2) {
        int n = n0 + nl;
        float acc = d_agg2[n * H2 + o] + bias2[o];
        #pragma unroll 4
        for (int i = 0; i < H1; ++i)
            acc = fmaf(h_s[nl][i], root2[i * H2 + o], acc);
        atomicAdd(&d_g[g_s[nl] * H2 + o], fmaxf(acc, 0.f));
    }
}

// ---------------- FCN head ---------------------------------------------------
__global__ void final1_kernel(const float* __restrict__ lin1_W,
                              const float* __restrict__ lin1_b)
{
    int idx = blockIdx.x * blockDim.x + threadIdx.x;
    if (idx < N_GRAPHS * F1) {
        int gi = idx / F1, oo = idx % F1;
        float acc = lin1_b[oo];
        #pragma unroll
        for (int i = 0; i < H2; ++i)
            acc = fmaf(d_g[gi * H2 + i], lin1_W[i * F1 + oo], acc);
        d_g1[idx] = fmaxf(acc, 0.f);
    }
}

__global__ void final2_kernel(const float* __restrict__ lin2_W,
                              const float* __restrict__ lin2_b,
                              float* __restrict__ out)
{
    int gi = blockIdx.x * blockDim.x + threadIdx.x;
    if (gi < N_GRAPHS) {
        float acc = lin2_b[0];
        #pragma unroll
        for (int j = 0; j < F1; ++j)
            acc = fmaf(d_g1[gi * F1 + j], lin2_W[j], acc);
        out[gi] = acc;
    }
}

// ---------------- launch -----------------------------------------------------
extern "C" void kernel_launch(void* const* d_in, const int* in_sizes, int n_in,
                              void* d_out, int out_size)
{
    const float* x      = (const float*)d_in[0];
    const float* ea     = (const float*)d_in[1];
    const void*  ei     = d_in[2];
    const void*  batch  = d_in[3];
    const float* nn1_W  = (const float*)d_in[4];
    const float* nn1_b  = (const float*)d_in[5];
    const float* root1  = (const float*)d_in[6];
    const float* bias1  = (const float*)d_in[7];
    const float* nn2_W  = (const float*)d_in[8];
    const float* nn2_b  = (const float*)d_in[9];
    const float* root2  = (const float*)d_in[10];
    const float* bias2  = (const float*)d_in[11];
    const float* lin1_W = (const float*)d_in[12];
    const float* lin1_b = (const float*)d_in[13];
    const float* lin2_W = (const float*)d_in[14];
    const float* lin2_b = (const float*)d_in[15];
    float* out = (float*)d_out;

    float *agg1, *agg2, *h1;
    cudaGetSymbolAddress((void**)&agg1, d_agg1);
    cudaGetSymbolAddress((void**)&agg2, d_agg2);
    cudaGetSymbolAddress((void**)&h1,   d_h1);

    detect_kernel<<<1, 256>>>((const unsigned int*)ei);
    zero_kernel<<<(Z_TOTAL + 255) / 256, 256>>>();

    // Layer 1: D=32, O=100. 625 blocks x 160 threads, per-thread 4x10 tile.
    edge_gemm<D_IN, H1, 64, 4, 10, 160><<<N_EDGES / 64, 160>>>(
        x, ea, ei, nn1_W, nn1_b, agg1);
    node1_kernel<<<N_NODES / 4, 512>>>(x, root1, bias1);

    // Layer 2: D=100, O=20. 625 blocks x 64 threads, per-thread 4x5 tile.
    edge_gemm<H1, H2, 64, 4, 5, 64><<<N_EDGES / 64, 64>>>(
        h1, ea, ei, nn2_W, nn2_b, agg2);
    node2_kernel<<<N_NODES / 8, 256>>>(root2, bias2, batch);

    final1_kernel<<<(N_GRAPHS * F1 + 255) / 256, 256>>>(lin1_W, lin1_b);
    final2_kernel<<<2, 256>>>(lin2_W, lin2_b, out);
}

// round 2
// speedup vs baseline: 2.8722x; 2.8722x over previous
#include <cuda_runtime.h>

#define N_NODES  20000
#define N_EDGES  40000
#define N_GRAPHS 500
#define D_IN     32
#define D_E      16
#define H1       100
#define H2       20
#define F1       50

#define NB1 1800   // 16*H1 edge-W | H1 bias | H1 root
#define NB2 360    // 16*H2 | H2 | H2

// ---------------- scratch ---------------------------------------------------
__device__ __align__(128) float d_B1t[D_IN * NB1];
__device__ __align__(128) float d_B2t[H1 * NB2];
__device__ __align__(128) float d_Y1 [(size_t)N_NODES * NB1];
__device__ __align__(128) float d_Y2 [(size_t)N_NODES * NB2];
__device__ __align__(128) float d_agg1[N_NODES * H1];
__device__ __align__(128) float d_h1  [N_NODES * H1];
__device__ __align__(128) float d_agg2[N_NODES * H2];
__device__ __align__(128) float d_g   [N_GRAPHS * H2];
__device__ __align__(128) float d_g1  [N_GRAPHS * F1];
__device__ int   d_is64;

// ---------------- packed f32x2 helpers --------------------------------------
__device__ __forceinline__ unsigned long long pk2(float lo, float hi) {
    unsigned long long r;
    asm("mov.b64 %0, {%1,%2};" : "=l"(r) : "f"(lo), "f"(hi));
    return r;
}
__device__ __forceinline__ unsigned long long ffma2(
    unsigned long long a, unsigned long long b, unsigned long long c) {
    unsigned long long d;
    asm("fma.rn.f32x2 %0, %1, %2, %3;" : "=l"(d) : "l"(a), "l"(b), "l"(c));
    return d;
}
__device__ __forceinline__ float2 unpk(unsigned long long v) {
    float2 f;
    asm("mov.b64 {%0,%1}, %2;" : "=f"(f.x), "=f"(f.y) : "l"(v));
    return f;
}

// ---------------- int32/int64 index detection -------------------------------
__global__ void detect_kernel(const unsigned int* __restrict__ ei_words) {
    __shared__ unsigned int red[256];
    unsigned int v = 0;
    for (int i = threadIdx.x; i < N_EDGES; i += blockDim.x)
        v |= ei_words[2 * i + 1];
    red[threadIdx.x] = v;
    __syncthreads();
    for (int s = 128; s > 0; s >>= 1) {
        if (threadIdx.x < s) red[threadIdx.x] |= red[threadIdx.x + s];
        __syncthreads();
    }
    if (threadIdx.x == 0) d_is64 = (red[0] == 0u) ? 1 : 0;
}

// ---------------- build fused B matrices ------------------------------------
__global__ void prep1(const float* __restrict__ W, const float* __restrict__ b,
                      const float* __restrict__ root) {
    int idx = blockIdx.x * blockDim.x + threadIdx.x;
    if (idx >= D_IN * NB1) return;
    int i = idx / NB1, j = idx % NB1;
    float v;
    if (j < 16 * H1)      { int k = j / H1, o = j % H1; v = W[k * (D_IN * H1) + i * H1 + o]; }
    else if (j < 17 * H1) { int o = j - 16 * H1;        v = b[i * H1 + o]; }
    else                  { int o = j - 17 * H1;        v = root[i * H1 + o]; }
    d_B1t[idx] = v;
}
__global__ void prep2(const float* __restrict__ W, const float* __restrict__ b,
                      const float* __restrict__ root) {
    int idx = blockIdx.x * blockDim.x + threadIdx.x;
    if (idx >= H1 * NB2) return;
    int i = idx / NB2, j = idx % NB2;
    float v;
    if (j < 16 * H2)      { int k = j / H2, o = j % H2; v = W[k * (H1 * H2) + i * H2 + o]; }
    else if (j < 17 * H2) { int o = j - 16 * H2;        v = b[i * H2 + o]; }
    else                  { int o = j - 17 * H2;        v = root[i * H2 + o]; }
    d_B2t[idx] = v;
}

// ---------------- zero accumulators -----------------------------------------
#define Z_TOTAL (N_NODES * H1 + N_NODES * H2 + N_GRAPHS * H2)
__global__ void zero_kernel() {
    int i = blockIdx.x * blockDim.x + threadIdx.x;
    if (i < N_NODES * H1) d_agg1[i] = 0.f;
    else if (i < N_NODES * H1 + N_NODES * H2) d_agg2[i - N_NODES * H1] = 0.f;
    else if (i < Z_TOTAL) d_g[i - N_NODES * H1 - N_NODES * H2] = 0.f;
}

// ---------------- f32x2 tiled GEMM: C[M,N] = A[M,K] @ B[K,N] -----------------
// BM=128, BN=64, BK=16, 128 threads, per-thread 8x8 via packed-f32x2 FMA.
template<int BM, int BN, int BK>
__global__ void __launch_bounds__(128) gemm_f32x2(
    const float* __restrict__ A, int M, int K,
    const float* __restrict__ B, int N,
    float* __restrict__ C)
{
    __shared__ float As[BK][BM + 4];
    __shared__ float Bs[BK][BN];

    const int tid  = threadIdx.x;
    const int tx   = tid & 7;    // col group (8 cols)
    const int ty   = tid >> 3;   // row group (8 rows)
    const int row0 = blockIdx.y * BM;
    const int col0 = blockIdx.x * BN;

    unsigned long long acc[8][4];
    #pragma unroll
    for (int i = 0; i < 8; i++)
        #pragma unroll
        for (int j = 0; j < 4; j++) acc[i][j] = 0ull;

    for (int k0 = 0; k0 < K; k0 += BK) {
        #pragma unroll
        for (int s = tid; s < BM * BK; s += 128) {
            int r = s / BK, kk = s % BK;
            int gr = row0 + r, gk = k0 + kk;
            As[kk][r] = (gr < M && gk < K) ? A[(size_t)gr * K + gk] : 0.f;
        }
        #pragma unroll
        for (int s = tid; s < BK * BN; s += 128) {
            int kk = s / BN, c = s % BN;
            int gk = k0 + kk, gc = col0 + c;
            Bs[kk][c] = (gk < K && gc < N) ? B[(size_t)gk * N + gc] : 0.f;
        }
        __syncthreads();
        #pragma unroll
        for (int kk = 0; kk < BK; kk++) {
            float4 alo = *(const float4*)&As[kk][ty * 8];
            float4 ahi = *(const float4*)&As[kk][ty * 8 + 4];
            float4 blo = *(const float4*)&Bs[kk][tx * 8];
            float4 bhi = *(const float4*)&Bs[kk][tx * 8 + 4];
            unsigned long long b2[4] = {
                pk2(blo.x, blo.y), pk2(blo.z, blo.w),
                pk2(bhi.x, bhi.y), pk2(bhi.z, bhi.w)
            };
            float av[8] = {alo.x, alo.y, alo.z, alo.w, ahi.x, ahi.y, ahi.z, ahi.w};
            #pragma unroll
            for (int i = 0; i < 8; i++) {
                unsigned long long a2 = pk2(av[i], av[i]);
                #pragma unroll
                for (int j = 0; j < 4; j++)
                    acc[i][j] = ffma2(a2, b2[j], acc[i][j]);
            }
        }
        __syncthreads();
    }

    #pragma unroll
    for (int i = 0; i < 8; i++) {
        int r = row0 + ty * 8 + i;
        if (r < M) {
            #pragma unroll
            for (int jj = 0; jj < 2; jj++) {
                int cc = col0 + tx * 8 + jj * 4;
                if (cc < N) {
                    float2 p0 = unpk(acc[i][jj * 2]);
                    float2 p1 = unpk(acc[i][jj * 2 + 1]);
                    *(float4*)&C[(size_t)r * N + cc] = make_float4(p0.x, p0.y, p1.x, p1.y);
                }
            }
        }
    }
}

// ---------------- edge combine + scatter, layer 1 ----------------------------
__global__ void __launch_bounds__(256) combine1(
    const float* __restrict__ ea, const void* __restrict__ ei_raw)
{
    __shared__ float ea_s[2][17];
    __shared__ int src_s[2], dst_s[2];
    int tid = threadIdx.x;
    int el  = tid >> 7;
    int o   = tid & 127;
    int e   = blockIdx.x * 2 + el;
    if (o < 17) ea_s[el][o] = (o < 16) ? ea[e * D_E + o] : 1.f;
    if (o == 17) {
        if (d_is64) {
            const long long* p = (const long long*)ei_raw;
            src_s[el] = (int)p[e]; dst_s[el] = (int)p[N_EDGES + e];
        } else {
            const int* p = (const int*)ei_raw;
            src_s[el] = p[e]; dst_s[el] = p[N_EDGES + e];
        }
    }
    __syncthreads();
    if (o < H1) {
        const float* yrow = d_Y1 + (size_t)src_s[el] * NB1 + o;
        float acc = 0.f;
        #pragma unroll
        for (int k = 0; k < 17; k++)
            acc = fmaf(ea_s[el][k], yrow[k * H1], acc);
        atomicAdd(&d_agg1[dst_s[el] * H1 + o], acc);
    }
}

// ---------------- node update 1 (elementwise: root GEMM lives in Y1) --------
__global__ void node1ew(const float* __restrict__ bias1) {
    int idx = blockIdx.x * blockDim.x + threadIdx.x;
    if (idx < N_NODES * H1) {
        int n = idx / H1, o = idx % H1;
        float v = d_agg1[idx] + d_Y1[(size_t)n * NB1 + 17 * H1 + o] + bias1[o];
        d_h1[idx] = fmaxf(v, 0.f);
    }
}

// ---------------- edge combine + scatter, layer 2 ----------------------------
__global__ void __launch_bounds__(256) combine2(
    const float* __restrict__ ea, const void* __restrict__ ei_raw)
{
    __shared__ float ea_s[8][17];
    __shared__ int src_s[8], dst_s[8];
    int tid = threadIdx.x;
    int el  = tid >> 5;
    int o   = tid & 31;
    int e   = blockIdx.x * 8 + el;
    if (o < 17) ea_s[el][o] = (o < 16) ? ea[e * D_E + o] : 1.f;
    if (o == 17) {
        if (d_is64) {
            const long long* p = (const long long*)ei_raw;
            src_s[el] = (int)p[e]; dst_s[el] = (int)p[N_EDGES + e];
        } else {
            const int* p = (const int*)ei_raw;
            src_s[el] = p[e]; dst_s[el] = p[N_EDGES + e];
        }
    }
    __syncthreads();
    if (o < H2) {
        const float* yrow = d_Y2 + (size_t)src_s[el] * NB2 + o;
        float acc = 0.f;
        #pragma unroll
        for (int k = 0; k < 17; k++)
            acc = fmaf(ea_s[el][k], yrow[k * H2], acc);
        atomicAdd(&d_agg2[dst_s[el] * H2 + o], acc);
    }
}

// ---------------- node update 2 + sum-pool ------------------------------------
__global__ void __launch_bounds__(256) node2pool(
    const float* __restrict__ bias2, const void* __restrict__ batch_raw)
{
    int tid = threadIdx.x;
    int nl  = tid >> 5;
    int o   = tid & 31;
    int n   = blockIdx.x * 8 + nl;
    if (o < H2) {
        float v = d_agg2[n * H2 + o] + d_Y2[(size_t)n * NB2 + 17 * H2 + o] + bias2[o];
        v = fmaxf(v, 0.f);
        int g = d_is64 ? (int)((const long long*)batch_raw)[n]
                       : ((const int*)batch_raw)[n];
        atomicAdd(&d_g[g * H2 + o], v);
    }
}

// ---------------- FCN head -----------------------------------------------------
__global__ void final1_kernel(const float* __restrict__ lin1_W,
                              const float* __restrict__ lin1_b)
{
    int idx = blockIdx.x * blockDim.x + threadIdx.x;
    if (idx < N_GRAPHS * F1) {
        int gi = idx / F1, oo = idx % F1;
        float acc = lin1_b[oo];
        #pragma unroll
        for (int i = 0; i < H2; ++i)
            acc = fmaf(d_g[gi * H2 + i], lin1_W[i * F1 + oo], acc);
        d_g1[idx] = fmaxf(acc, 0.f);
    }
}

__global__ void final2_kernel(const float* __restrict__ lin2_W,
                              const float* __restrict__ lin2_b,
                              float* __restrict__ out)
{
    int gi = blockIdx.x * blockDim.x + threadIdx.x;
    if (gi < N_GRAPHS) {
        float acc = lin2_b[0];
        #pragma unroll
        for (int j = 0; j < F1; ++j)
            acc = fmaf(d_g1[gi * F1 + j], lin2_W[j], acc);
        out[gi] = acc;
    }
}

// ---------------- launch ---------------------------------------------------------
extern "C" void kernel_launch(void* const* d_in, const int* in_sizes, int n_in,
                              void* d_out, int out_size)
{
    const float* x      = (const float*)d_in[0];
    const float* ea     = (const float*)d_in[1];
    const void*  ei     = d_in[2];
    const void*  batch  = d_in[3];
    const float* nn1_W  = (const float*)d_in[4];
    const float* nn1_b  = (const float*)d_in[5];
    const float* root1  = (const float*)d_in[6];
    const float* bias1  = (const float*)d_in[7];
    const float* nn2_W  = (const float*)d_in[8];
    const float* nn2_b  = (const float*)d_in[9];
    const float* root2  = (const float*)d_in[10];
    const float* bias2  = (const float*)d_in[11];
    const float* lin1_W = (const float*)d_in[12];
    const float* lin1_b = (const float*)d_in[13];
    const float* lin2_W = (const float*)d_in[14];
    const float* lin2_b = (const float*)d_in[15];
    float* out = (float*)d_out;

    float *B1t, *B2t, *Y1, *Y2, *h1;
    cudaGetSymbolAddress((void**)&B1t, d_B1t);
    cudaGetSymbolAddress((void**)&B2t, d_B2t);
    cudaGetSymbolAddress((void**)&Y1,  d_Y1);
    cudaGetSymbolAddress((void**)&Y2,  d_Y2);
    cudaGetSymbolAddress((void**)&h1,  d_h1);

    detect_kernel<<<1, 256>>>((const unsigned int*)ei);
    prep1<<<(D_IN * NB1 + 255) / 256, 256>>>(nn1_W, nn1_b, root1);
    prep2<<<(H1 * NB2 + 255) / 256, 256>>>(nn2_W, nn2_b, root2);
    zero_kernel<<<(Z_TOTAL + 255) / 256, 256>>>();

    // Y1[20000,1800] = x[20000,32] @ B1t[32,1800]
    gemm_f32x2<128, 64, 16><<<dim3((NB1 + 63) / 64, (N_NODES + 127) / 128), 128>>>(
        x, N_NODES, D_IN, B1t, NB1, Y1);
    combine1<<<N_EDGES / 2, 256>>>(ea, ei);
    node1ew<<<(N_NODES * H1 + 255) / 256, 256>>>(bias1);

    // Y2[20000,360] = h1[20000,100] @ B2t[100,360]
    gemm_f32x2<128, 64, 16><<<dim3((NB2 + 63) / 64, (N_NODES + 127) / 128), 128>>>(
        h1, N_NODES, H1, B2t, NB2, Y2);
    combine2<<<N_EDGES / 8, 256>>>(ea, ei);
    node2pool<<<N_NODES / 8, 256>>>(bias2, batch);

    final1_kernel<<<(N_GRAPHS * F1 + 255) / 256, 256>>>(lin1_W, lin1_b);
    final2_kernel<<<2, 256>>>(lin2_W, lin2_b, out);
}